// round 1
// baseline (speedup 1.0000x reference)
#include <cuda_runtime.h>
#include <cstdint>
#include <math.h>

#define FULLMASK 0xFFFFFFFFu

constexpr int Bz = 8, Np = 4096, Cch = 64, Kn = 30;
constexpr int Mtot = Bz * Np * Kn;           // 983040
constexpr float EPS_BN = 1e-5f;
constexpr float TINYc = 1e-20f;

constexpr int KNN_WARPS = 8;
constexpr int CAND_MAX = 512;

// ---------------- scratch (static device globals; no runtime allocation) ----
__device__ float4 g_pts4[Bz * Np];           // x,y,z,|p|^2
__device__ float  g_xT[Bz * Np * Cch];       // x transposed to [B,N,C]
__device__ int    g_idx[Mtot];               // knn indices
__device__ float  g_h1[6 * Mtot];            // layer1 pre-BN, SoA [c][e]
__device__ float  g_h2[3 * Mtot];
__device__ float  g_h3[Mtot];
__device__ double g_stats[24];               // L1: sum[0:6] sq[6:12]; L2: 12..17; L3: 18,19

// ---------------- K0: zero stats, build pts4 and xT ------------------------
__global__ void __launch_bounds__(256) k_init(const float* __restrict__ xloc,
                                              const float* __restrict__ x) {
    int t = blockIdx.x * blockDim.x + threadIdx.x;
    int stride = gridDim.x * blockDim.x;
    if (t < 24) g_stats[t] = 0.0;
    for (int i = t; i < Bz * Np; i += stride) {
        int b = i >> 12, n = i & 4095;
        const float* p = xloc + b * 3 * Np;
        float px = p[n], py = p[Np + n], pz = p[2 * Np + n];
        float xx = fmaf(pz, pz, fmaf(py, py, px * px));
        g_pts4[i] = make_float4(px, py, pz, xx);
    }
    for (int i = t; i < Bz * Cch * Np; i += stride) {
        int n = i & 4095;
        int c = (i >> 12) & 63;
        int b = i >> 18;
        g_xT[(b * Np + n) * Cch + c] = x[i];
    }
}

// ---------------- K1: KNN via per-warp radix-select ------------------------
struct WarpSel {
    unsigned hist[256];
    unsigned candKey[CAND_MAX];
    unsigned res[32];
    unsigned short candIdx[CAND_MAX];
    unsigned cntRes, cntCand;
};

__device__ __forceinline__ unsigned pdKey(float4 q, float4 pj) {
    // pd = 2<q,p> - |q|^2 - |p|^2 = -dist^2 ; order-preserving uint key
    float dot = fmaf(q.z, pj.z, fmaf(q.y, pj.y, q.x * pj.x));
    float pd = fmaf(2.0f, dot, -q.w) - pj.w;
    unsigned bts = __float_as_uint(pd);
    return bts ^ ((unsigned)((int)bts >> 31) | 0x80000000u);
}

__global__ void __launch_bounds__(256) k_knn() {
    extern __shared__ unsigned char smemRaw[];
    float4* sPts = reinterpret_cast<float4*>(smemRaw);
    WarpSel* selArr = reinterpret_cast<WarpSel*>(smemRaw + sizeof(float4) * Np);

    int b = blockIdx.y;
    const float4* gp = g_pts4 + b * Np;
    for (int i = threadIdx.x; i < Np; i += blockDim.x) sPts[i] = gp[i];
    __syncthreads();

    int wid = threadIdx.x >> 5, lane = threadIdx.x & 31;
    WarpSel& W = selArr[wid];
    int wpb = gridDim.x * KNN_WARPS;

    for (int n = blockIdx.x * KNN_WARPS + wid; n < Np; n += wpb) {
        float4 q = sPts[n];
        unsigned P = 0; int pl = 0; int need = Kn;

        // radix descend: find byte-prefix threshold so boundary bin <= CAND_MAX
        while (true) {
            for (int h = lane; h < 256; h += 32) W.hist[h] = 0;
            __syncwarp();
            unsigned sh1 = (unsigned)(32 - pl);
            int sh2 = 24 - pl;
            for (int j = lane; j < Np; j += 32) {
                unsigned key = pdKey(q, sPts[j]);
                bool m = true;
                if (pl != 0) m = ((key >> sh1) == P);
                int bytev = m ? (int)((key >> sh2) & 0xFFu) : 256;
                unsigned grp = __match_any_sync(FULLMASK, bytev);  // aggregate atomics
                if (m && lane == (__ffs(grp) - 1))
                    atomicAdd(&W.hist[bytev], (unsigned)__popc(grp));
            }
            __syncwarp();
            // suffix counts over 256 bins (8 bins per lane)
            int base = lane * 8;
            int s = 0;
            #pragma unroll
            for (int t = 0; t < 8; t++) s += (int)W.hist[base + t];
            int suf = s;
            #pragma unroll
            for (int off = 1; off < 32; off <<= 1) {
                int v = __shfl_down_sync(FULLMASK, suf, off);
                if (lane + off < 32) suf += v;
            }
            int sufN = __shfl_down_sync(FULLMASK, suf, 1);
            if (lane == 31) sufN = 0;
            bool isL = (suf >= need) && (sufN < need);
            unsigned mb = __ballot_sync(FULLMASK, isL);
            int L = __ffs(mb) - 1;
            int T = 0, above = 0, hT = 0;
            if (lane == L) {
                int cnt = sufN;
                for (int bb = base + 7; bb >= base; bb--) {
                    int hh = (int)W.hist[bb];
                    if (cnt + hh >= need) { T = bb; above = cnt; hT = hh; break; }
                    cnt += hh;
                }
            }
            T = __shfl_sync(FULLMASK, T, L);
            above = __shfl_sync(FULLMASK, above, L);
            hT = __shfl_sync(FULLMASK, hT, L);
            P = (P << 8) | (unsigned)T;
            pl += 8;
            need -= above;                      // keys strictly above T are in top-k
            if (hT <= CAND_MAX || pl == 32) break;
        }

        // collection pass
        if (lane == 0) { W.cntRes = 0; W.cntCand = 0; }
        __syncwarp();
        unsigned sh = (unsigned)(32 - pl);
        for (int j = lane; j < Np; j += 32) {
            unsigned key = pdKey(q, sPts[j]);
            unsigned kq = (pl == 32) ? key : (key >> sh);
            if (kq > P) {
                unsigned p = atomicAdd(&W.cntRes, 1u);
                W.res[p] = (unsigned)j;
            } else if (kq == P) {
                unsigned p = atomicAdd(&W.cntCand, 1u);
                if (p < CAND_MAX) { W.candKey[p] = key; W.candIdx[p] = (unsigned short)j; }
            }
        }
        __syncwarp();
        int A = (int)W.cntRes;
        int Ccand = min((int)W.cntCand, CAND_MAX);
        // extract 'need' largest from boundary-bin candidates
        for (int r = 0; r < need; r++) {
            unsigned best = 0; int bi = -1;
            for (int t = lane; t < Ccand; t += 32) {
                unsigned kk = W.candKey[t];
                if (kk > best) { best = kk; bi = t; }
            }
            #pragma unroll
            for (int off = 16; off; off >>= 1) {
                unsigned ob = __shfl_down_sync(FULLMASK, best, off);
                int oi = __shfl_down_sync(FULLMASK, bi, off);
                if (ob > best) { best = ob; bi = oi; }
            }
            bi = __shfl_sync(FULLMASK, bi, 0);
            if (lane == 0) { W.res[A + r] = W.candIdx[bi]; W.candKey[bi] = 0; }
            __syncwarp();
        }
        if (lane < Kn) g_idx[(b * Np + n) * Kn + lane] = (int)W.res[lane];
        __syncwarp();
    }
}

// ---------------- block-level stat accumulation ----------------------------
template <int NV>
__device__ __forceinline__ void accumStats(const float* vals, float* sAcc, int statBase) {
    #pragma unroll
    for (int v = 0; v < NV; v++) {
        float x = vals[v];
        #pragma unroll
        for (int off = 16; off; off >>= 1) x += __shfl_down_sync(FULLMASK, x, off);
        if ((threadIdx.x & 31) == 0) atomicAdd(&sAcc[v], x);
    }
    __syncthreads();
    if (threadIdx.x < NV) atomicAdd(&g_stats[statBase + threadIdx.x], (double)sAcc[threadIdx.x]);
}

// ---------------- K2: spherical features + layer1 + stats ------------------
__global__ void __launch_bounds__(256) k_feat(const float* __restrict__ W1) {
    __shared__ float sW[36];
    __shared__ float sAcc[12];
    int tid = threadIdx.x;
    if (tid < 36) sW[tid] = W1[tid];
    if (tid < 12) sAcc[tid] = 0.f;
    __syncthreads();
    int wid = tid >> 5, lane = tid & 31;
    int r = blockIdx.x * 8 + wid;            // row = b*Np+n
    int b = r >> 12;
    float vals[12];
    #pragma unroll
    for (int v = 0; v < 12; v++) vals[v] = 0.f;
    if (lane < Kn) {
        int e = r * Kn + lane;
        int j = g_idx[e];
        float4 pn = g_pts4[r];
        float4 pj = g_pts4[(b << 12) + j];
        float xr = pj.x - pn.x, yr = pj.y - pn.y, zr = pj.z - pn.z;
        float sxy2 = fmaf(yr, yr, xr * xr);
        float r2 = fmaf(zr, zr, sxy2);
        float rho = sqrtf(fmaxf(r2, TINYc));
        float sxy = sqrtf(fmaxf(sxy2, TINYc));
        float theta = (r2 < TINYc) ? 0.f : atan2f(zr, sxy);
        float phi = (sxy2 < TINYc) ? 0.f : atan2f(yr, xr);
        float mn = (rho + theta + phi) * (1.f / 3.f);
        float f[6] = {rho, theta, phi, rho - mn, theta - mn, phi - mn};
        #pragma unroll
        for (int o = 0; o < 6; o++) {
            float h = 0.f;
            #pragma unroll
            for (int i2 = 0; i2 < 6; i2++) h = fmaf(sW[o * 6 + i2], f[i2], h);
            g_h1[o * Mtot + e] = h;
            vals[o] = h; vals[6 + o] = h * h;
        }
    }
    accumStats<12>(vals, sAcc, 0);
}

// ---------------- K3: BN1 + lrelu + layer2 + stats -------------------------
__global__ void __launch_bounds__(256) k_l2(const float* __restrict__ gma,
                                            const float* __restrict__ bta,
                                            const float* __restrict__ W2) {
    __shared__ float sMu[6], sIs[6], sG[6], sB[6], sW[18], sAcc[6];
    int tid = threadIdx.x;
    if (tid < 6) {
        double s = g_stats[tid], sq = g_stats[6 + tid];
        double mu = s / (double)Mtot;
        double var = sq / (double)Mtot - mu * mu;
        sMu[tid] = (float)mu;
        sIs[tid] = (float)(1.0 / sqrt(var + (double)EPS_BN));
        sG[tid] = gma[tid]; sB[tid] = bta[tid];
        sAcc[tid] = 0.f;
    }
    if (tid < 18) sW[tid] = W2[tid];
    __syncthreads();
    int e = blockIdx.x * 256 + tid;
    float a[6];
    #pragma unroll
    for (int i = 0; i < 6; i++) {
        float h = g_h1[i * Mtot + e];
        float t = fmaf((h - sMu[i]) * sIs[i], sG[i], sB[i]);
        a[i] = t > 0.f ? t : 0.2f * t;
    }
    float vals[6];
    #pragma unroll
    for (int o = 0; o < 3; o++) {
        float h = 0.f;
        #pragma unroll
        for (int i = 0; i < 6; i++) h = fmaf(sW[o * 6 + i], a[i], h);
        g_h2[o * Mtot + e] = h;
        vals[o] = h; vals[3 + o] = h * h;
    }
    accumStats<6>(vals, sAcc, 12);
}

// ---------------- K4: BN2 + lrelu + layer3 + stats -------------------------
__global__ void __launch_bounds__(256) k_l3(const float* __restrict__ gma,
                                            const float* __restrict__ bta,
                                            const float* __restrict__ W3) {
    __shared__ float sMu[3], sIs[3], sG[3], sB[3], sW[3], sAcc[2];
    int tid = threadIdx.x;
    if (tid < 3) {
        double s = g_stats[12 + tid], sq = g_stats[15 + tid];
        double mu = s / (double)Mtot;
        double var = sq / (double)Mtot - mu * mu;
        sMu[tid] = (float)mu;
        sIs[tid] = (float)(1.0 / sqrt(var + (double)EPS_BN));
        sG[tid] = gma[tid]; sB[tid] = bta[tid];
        sW[tid] = W3[tid];
    }
    if (tid < 2) sAcc[tid] = 0.f;
    __syncthreads();
    int e = blockIdx.x * 256 + tid;
    float h = 0.f;
    #pragma unroll
    for (int i = 0; i < 3; i++) {
        float hv = g_h2[i * Mtot + e];
        float t = fmaf((hv - sMu[i]) * sIs[i], sG[i], sB[i]);
        float a = t > 0.f ? t : 0.2f * t;
        h = fmaf(sW[i], a, h);
    }
    g_h3[e] = h;
    float vals[2] = {h, h * h};
    accumStats<2>(vals, sAcc, 18);
}

// ---------------- K5: BN3 + lrelu + softmax + aggregate --------------------
__global__ void __launch_bounds__(256) k_out(const float* __restrict__ x,
                                             const float* __restrict__ g3,
                                             const float* __restrict__ b3,
                                             float* __restrict__ out) {
    __shared__ float sAtt[8][Kn];
    __shared__ int sJ[8][Kn];
    __shared__ float sMu, sIs;
    int tid = threadIdx.x, wid = tid >> 5, lane = tid & 31;
    if (tid == 0) {
        double s = g_stats[18], sq = g_stats[19];
        double mu = s / (double)Mtot;
        double var = sq / (double)Mtot - mu * mu;
        sMu = (float)mu;
        sIs = (float)(1.0 / sqrt(var + (double)EPS_BN));
    }
    __syncthreads();
    int r = blockIdx.x * 8 + wid;
    int b = r >> 12, n = r & 4095;
    float gv = g3[0], bv = b3[0];
    float logit = -INFINITY;
    if (lane < Kn) {
        float h = g_h3[r * Kn + lane];
        float t = fmaf((h - sMu) * sIs, gv, bv);
        logit = t > 0.f ? t : 0.2f * t;
    }
    float mx = logit;
    #pragma unroll
    for (int off = 16; off; off >>= 1) mx = fmaxf(mx, __shfl_xor_sync(FULLMASK, mx, off));
    float ex = (lane < Kn) ? expf(logit - mx) : 0.f;
    float sm = ex;
    #pragma unroll
    for (int off = 16; off; off >>= 1) sm += __shfl_xor_sync(FULLMASK, sm, off);
    float att = ex / sm;
    if (lane < Kn) {
        sAtt[wid][lane] = att;
        sJ[wid][lane] = g_idx[r * Kn + lane];
    }
    __syncwarp();
    float acc0 = 0.f, acc1 = 0.f;
    const float* xb = g_xT + (size_t)(b << 12) * Cch;
    #pragma unroll 5
    for (int kk = 0; kk < Kn; kk++) {
        const float* p = xb + sJ[wid][kk] * Cch;
        float a = sAtt[wid][kk];
        acc0 = fmaf(a, p[lane], acc0);
        acc1 = fmaf(a, p[lane + 32], acc1);
    }
    size_t o0 = (size_t)b * (Cch * Np) + (size_t)lane * Np + (size_t)n;
    size_t o1 = o0 + (size_t)32 * Np;
    out[o0] = x[o0] + acc0;
    out[o1] = x[o1] + acc1;
}

// ---------------- launch ----------------------------------------------------
extern "C" void kernel_launch(void* const* d_in, const int* in_sizes, int n_in,
                              void* d_out, int out_size) {
    const float* xloc = (const float*)d_in[0];
    const float* x    = (const float*)d_in[1];
    const float* W1   = (const float*)d_in[2];
    const float* g1   = (const float*)d_in[3];
    const float* b1   = (const float*)d_in[4];
    const float* W2   = (const float*)d_in[5];
    const float* g2   = (const float*)d_in[6];
    const float* b2   = (const float*)d_in[7];
    const float* W3   = (const float*)d_in[8];
    const float* g3   = (const float*)d_in[9];
    const float* b3   = (const float*)d_in[10];
    float* out = (float*)d_out;

    size_t knnSmem = sizeof(float4) * Np + sizeof(WarpSel) * KNN_WARPS;
    cudaFuncSetAttribute(k_knn, cudaFuncAttributeMaxDynamicSharedMemorySize, (int)knnSmem);

    k_init<<<2048, 256>>>(xloc, x);
    k_knn<<<dim3(37, 8), 256, knnSmem>>>();
    k_feat<<<Bz * Np / 8, 256>>>(W1);
    k_l2<<<Mtot / 256, 256>>>(g1, b1, W2);
    k_l3<<<Mtot / 256, 256>>>(g2, b2, W3);
    k_out<<<Bz * Np / 8, 256>>>(x, g3, b3, out);
}

// round 2
// speedup vs baseline: 1.4475x; 1.4475x over previous
#include <cuda_runtime.h>
#include <cstdint>
#include <math.h>

#define FULLMASK 0xFFFFFFFFu

constexpr int Bz = 8, Np = 4096, Cch = 64, Kn = 30;
constexpr int Mtot = Bz * Np * Kn;           // 983040
constexpr float EPS_BN = 1e-5f;
constexpr float TINYc = 1e-20f;

constexpr int KNN_WARPS = 8;
constexpr int CAND_MAX = 512;

// ---------------- scratch (static device globals; no runtime allocation) ----
__device__ float4 g_pts4[Bz * Np];           // x,y,z,|p|^2
__device__ float  g_xT[Bz * Np * Cch];       // x transposed to [B,N,C]
__device__ int    g_idx[Mtot];               // knn indices
__device__ float  g_h1[6 * Mtot];            // layer1 pre-BN, SoA [c][e]
__device__ float  g_h2[3 * Mtot];
__device__ float  g_h3[Mtot];
__device__ double g_stats[24];               // L1: sum[0:6] sq[6:12]; L2: 12..17; L3: 18,19

// ---------------- K0: zero stats, build pts4 -------------------------------
__global__ void __launch_bounds__(256) k_init(const float* __restrict__ xloc) {
    int t = blockIdx.x * blockDim.x + threadIdx.x;
    int stride = gridDim.x * blockDim.x;
    if (t < 24) g_stats[t] = 0.0;
    for (int i = t; i < Bz * Np; i += stride) {
        int b = i >> 12, n = i & 4095;
        const float* p = xloc + b * 3 * Np;
        float px = p[n], py = p[Np + n], pz = p[2 * Np + n];
        float xx = fmaf(pz, pz, fmaf(py, py, px * px));
        g_pts4[i] = make_float4(px, py, pz, xx);
    }
}

// ---------------- K0b: tiled transpose x -> xT [B,N,C] ---------------------
__global__ void __launch_bounds__(256) k_xt(const float* __restrict__ x) {
    __shared__ float s[64][33];
    int b = blockIdx.y;
    int n0 = blockIdx.x * 32;
    int lane = threadIdx.x & 31, w = threadIdx.x >> 5;
    #pragma unroll
    for (int i = 0; i < 8; i++) {
        int c = w * 8 + i;
        s[c][lane] = x[(((b << 6) + c) << 12) + n0 + lane];
    }
    __syncthreads();
    #pragma unroll
    for (int i = 0; i < 8; i++) {
        int e = i * 256 + threadIdx.x;
        int nl = e >> 6, c = e & 63;
        g_xT[(size_t)(((b << 12) + n0 + nl) << 6) + c] = s[c][nl];
    }
}

// ---------------- K1: KNN via sample-threshold + rank select ---------------
struct WarpSel {
    unsigned long long cand[CAND_MAX];
};

__device__ __forceinline__ float pdF(float4 q, float4 p) {
    float dot = fmaf(q.z, p.z, fmaf(q.y, p.y, q.x * p.x));
    return fmaf(2.0f, dot, -q.w) - p.w;
}
__device__ __forceinline__ unsigned fkeyU(float f) {
    unsigned b = __float_as_uint(f);
    return b ^ ((unsigned)((int)b >> 31) | 0x80000000u);
}

__global__ void __launch_bounds__(256, 2) k_knn() {
    extern __shared__ unsigned char smemRaw[];
    float4* sPts = reinterpret_cast<float4*>(smemRaw);
    WarpSel* selA = reinterpret_cast<WarpSel*>(smemRaw + sizeof(float4) * Np);

    int b = blockIdx.y;
    const float4* gp = g_pts4 + b * Np;
    for (int i = threadIdx.x; i < Np; i += 256) sPts[i] = gp[i];
    __syncthreads();

    int wid = threadIdx.x >> 5, lane = threadIdx.x & 31;
    WarpSel& W = selA[wid];
    unsigned laneLT = (lane == 31) ? 0x7FFFFFFFu : ((1u << lane) - 1u);

    for (int n = blockIdx.x * KNN_WARPS + wid; n < Np; n += gridDim.x * KNN_WARPS) {
        float4 q = sPts[n];

        // --- sample pass: 512 points, per-lane top-2 ---
        float m1 = -3.4e38f, m2 = -3.4e38f;
        int off = n & 7;
        #pragma unroll 4
        for (int t = lane; t < 512; t += 32) {
            float pd = pdF(q, sPts[(t << 3) + off]);
            if (pd > m2) {
                if (pd > m1) { m2 = m1; m1 = pd; } else m2 = pd;
            }
        }
        // --- extract 12th & 24th largest of the 64 lane-top2 values ---
        float T12 = 0.f, T24 = 0.f;
        for (int r = 0; r < 24; r++) {
            float bv = m1; int bl = lane;
            #pragma unroll
            for (int o = 16; o; o >>= 1) {
                float ov = __shfl_xor_sync(FULLMASK, bv, o);
                int ol = __shfl_xor_sync(FULLMASK, bl, o);
                if (ov > bv || (ov == bv && ol < bl)) { bv = ov; bl = ol; }
            }
            if (r == 11) T12 = bv;
            if (r == 23) T24 = bv;
            if (lane == bl) { m1 = m2; m2 = -3.4e38f; }
        }

        // --- count+collect pass (ballot compaction, no atomics) ---
        float T = T12;
        int C;
        for (int attempt = 0; ; attempt++) {
            unsigned basec = 0;
            #pragma unroll 2
            for (int j = lane; j < Np; j += 32) {
                float pd = pdF(q, sPts[j]);
                bool hit = pd > T;
                unsigned msk = __ballot_sync(FULLMASK, hit);
                if (hit) {
                    unsigned p = basec + __popc(msk & laneLT);
                    if (p < CAND_MAX)
                        W.cand[p] = ((unsigned long long)fkeyU(pd) << 16) | (unsigned)j;
                }
                basec += __popc(msk);
            }
            C = min((int)basec, CAND_MAX);
            if (C >= Kn || attempt == 1) break;
            T = T24;   // rare undershoot: retry with looser threshold
        }
        __syncwarp();

        // --- rank-based top-30 selection (unique total order via packed idx) ---
        int base0 = (b * Np + n) * Kn;
        if (C < Kn) {                       // astronomically rare: pad with self
            if (lane < Kn) g_idx[base0 + lane] = n;
        }
        for (int tb = 0; tb < C; tb += 128) {
            int t0 = tb + lane;
            unsigned long long v0 = (t0 < C)      ? W.cand[t0]      : 0ULL;
            unsigned long long v1 = (t0 + 32 < C) ? W.cand[t0 + 32] : 0ULL;
            unsigned long long v2 = (t0 + 64 < C) ? W.cand[t0 + 64] : 0ULL;
            unsigned long long v3 = (t0 + 96 < C) ? W.cand[t0 + 96] : 0ULL;
            int r0 = 0, r1 = 0, r2 = 0, r3 = 0;
            #pragma unroll 4
            for (int s = 0; s < C; s++) {
                unsigned long long w2 = W.cand[s];
                r0 += (w2 > v0); r1 += (w2 > v1);
                r2 += (w2 > v2); r3 += (w2 > v3);
            }
            if (t0 < C      && r0 < Kn) g_idx[base0 + r0] = (int)(v0 & 0xFFFFULL);
            if (t0 + 32 < C && r1 < Kn) g_idx[base0 + r1] = (int)(v1 & 0xFFFFULL);
            if (t0 + 64 < C && r2 < Kn) g_idx[base0 + r2] = (int)(v2 & 0xFFFFULL);
            if (t0 + 96 < C && r3 < Kn) g_idx[base0 + r3] = (int)(v3 & 0xFFFFULL);
        }
        __syncwarp();
    }
}

// ---------------- block-level stat accumulation ----------------------------
template <int NV>
__device__ __forceinline__ void accumStats(const float* vals, float* sAcc, int statBase) {
    #pragma unroll
    for (int v = 0; v < NV; v++) {
        float x = vals[v];
        #pragma unroll
        for (int off = 16; off; off >>= 1) x += __shfl_down_sync(FULLMASK, x, off);
        if ((threadIdx.x & 31) == 0) atomicAdd(&sAcc[v], x);
    }
    __syncthreads();
    if (threadIdx.x < NV) atomicAdd(&g_stats[statBase + threadIdx.x], (double)sAcc[threadIdx.x]);
}

// ---------------- K2: spherical features + layer1 + stats ------------------
__global__ void __launch_bounds__(256) k_feat(const float* __restrict__ W1) {
    __shared__ float sW[36];
    __shared__ float sAcc[12];
    int tid = threadIdx.x;
    if (tid < 36) sW[tid] = W1[tid];
    if (tid < 12) sAcc[tid] = 0.f;
    __syncthreads();
    int wid = tid >> 5, lane = tid & 31;
    int r = blockIdx.x * 8 + wid;            // row = b*Np+n
    int b = r >> 12;
    float vals[12];
    #pragma unroll
    for (int v = 0; v < 12; v++) vals[v] = 0.f;
    if (lane < Kn) {
        int e = r * Kn + lane;
        int j = g_idx[e];
        float4 pn = g_pts4[r];
        float4 pj = g_pts4[(b << 12) + j];
        float xr = pj.x - pn.x, yr = pj.y - pn.y, zr = pj.z - pn.z;
        float sxy2 = fmaf(yr, yr, xr * xr);
        float r2 = fmaf(zr, zr, sxy2);
        float rho = sqrtf(fmaxf(r2, TINYc));
        float sxy = sqrtf(fmaxf(sxy2, TINYc));
        float theta = (r2 < TINYc) ? 0.f : atan2f(zr, sxy);
        float phi = (sxy2 < TINYc) ? 0.f : atan2f(yr, xr);
        float mn = (rho + theta + phi) * (1.f / 3.f);
        float f[6] = {rho, theta, phi, rho - mn, theta - mn, phi - mn};
        #pragma unroll
        for (int o = 0; o < 6; o++) {
            float h = 0.f;
            #pragma unroll
            for (int i2 = 0; i2 < 6; i2++) h = fmaf(sW[o * 6 + i2], f[i2], h);
            g_h1[o * Mtot + e] = h;
            vals[o] = h; vals[6 + o] = h * h;
        }
    }
    accumStats<12>(vals, sAcc, 0);
}

// ---------------- K3: BN1 + lrelu + layer2 + stats -------------------------
__global__ void __launch_bounds__(256) k_l2(const float* __restrict__ gma,
                                            const float* __restrict__ bta,
                                            const float* __restrict__ W2) {
    __shared__ float sMu[6], sIs[6], sG[6], sB[6], sW[18], sAcc[6];
    int tid = threadIdx.x;
    if (tid < 6) {
        double s = g_stats[tid], sq = g_stats[6 + tid];
        double mu = s / (double)Mtot;
        double var = sq / (double)Mtot - mu * mu;
        sMu[tid] = (float)mu;
        sIs[tid] = (float)(1.0 / sqrt(var + (double)EPS_BN));
        sG[tid] = gma[tid]; sB[tid] = bta[tid];
        sAcc[tid] = 0.f;
    }
    if (tid < 18) sW[tid] = W2[tid];
    __syncthreads();
    int e = blockIdx.x * 256 + tid;
    float a[6];
    #pragma unroll
    for (int i = 0; i < 6; i++) {
        float h = g_h1[i * Mtot + e];
        float t = fmaf((h - sMu[i]) * sIs[i], sG[i], sB[i]);
        a[i] = t > 0.f ? t : 0.2f * t;
    }
    float vals[6];
    #pragma unroll
    for (int o = 0; o < 3; o++) {
        float h = 0.f;
        #pragma unroll
        for (int i = 0; i < 6; i++) h = fmaf(sW[o * 6 + i], a[i], h);
        g_h2[o * Mtot + e] = h;
        vals[o] = h; vals[3 + o] = h * h;
    }
    accumStats<6>(vals, sAcc, 12);
}

// ---------------- K4: BN2 + lrelu + layer3 + stats -------------------------
__global__ void __launch_bounds__(256) k_l3(const float* __restrict__ gma,
                                            const float* __restrict__ bta,
                                            const float* __restrict__ W3) {
    __shared__ float sMu[3], sIs[3], sG[3], sB[3], sW[3], sAcc[2];
    int tid = threadIdx.x;
    if (tid < 3) {
        double s = g_stats[12 + tid], sq = g_stats[15 + tid];
        double mu = s / (double)Mtot;
        double var = sq / (double)Mtot - mu * mu;
        sMu[tid] = (float)mu;
        sIs[tid] = (float)(1.0 / sqrt(var + (double)EPS_BN));
        sG[tid] = gma[tid]; sB[tid] = bta[tid];
        sW[tid] = W3[tid];
    }
    if (tid < 2) sAcc[tid] = 0.f;
    __syncthreads();
    int e = blockIdx.x * 256 + tid;
    float h = 0.f;
    #pragma unroll
    for (int i = 0; i < 3; i++) {
        float hv = g_h2[i * Mtot + e];
        float t = fmaf((hv - sMu[i]) * sIs[i], sG[i], sB[i]);
        float a = t > 0.f ? t : 0.2f * t;
        h = fmaf(sW[i], a, h);
    }
    g_h3[e] = h;
    float vals[2] = {h, h * h};
    accumStats<2>(vals, sAcc, 18);
}

// ---------------- K5: BN3 + lrelu + softmax + aggregate --------------------
__global__ void __launch_bounds__(256) k_out(const float* __restrict__ x,
                                             const float* __restrict__ g3,
                                             const float* __restrict__ b3,
                                             float* __restrict__ out) {
    __shared__ float sAtt[8][Kn];
    __shared__ int sJ[8][Kn];
    __shared__ float sMu, sIs;
    int tid = threadIdx.x, wid = tid >> 5, lane = tid & 31;
    if (tid == 0) {
        double s = g_stats[18], sq = g_stats[19];
        double mu = s / (double)Mtot;
        double var = sq / (double)Mtot - mu * mu;
        sMu = (float)mu;
        sIs = (float)(1.0 / sqrt(var + (double)EPS_BN));
    }
    __syncthreads();
    int r = blockIdx.x * 8 + wid;
    int b = r >> 12, n = r & 4095;
    float gv = g3[0], bv = b3[0];
    float logit = -INFINITY;
    if (lane < Kn) {
        float h = g_h3[r * Kn + lane];
        float t = fmaf((h - sMu) * sIs, gv, bv);
        logit = t > 0.f ? t : 0.2f * t;
    }
    float mx = logit;
    #pragma unroll
    for (int off = 16; off; off >>= 1) mx = fmaxf(mx, __shfl_xor_sync(FULLMASK, mx, off));
    float ex = (lane < Kn) ? expf(logit - mx) : 0.f;
    float sm = ex;
    #pragma unroll
    for (int off = 16; off; off >>= 1) sm += __shfl_xor_sync(FULLMASK, sm, off);
    float att = ex / sm;
    if (lane < Kn) {
        sAtt[wid][lane] = att;
        sJ[wid][lane] = g_idx[r * Kn + lane];
    }
    __syncwarp();
    float acc0 = 0.f, acc1 = 0.f;
    const float* xb = g_xT + (size_t)(b << 12) * Cch;
    #pragma unroll 5
    for (int kk = 0; kk < Kn; kk++) {
        const float* p = xb + sJ[wid][kk] * Cch;
        float a = sAtt[wid][kk];
        acc0 = fmaf(a, p[lane], acc0);
        acc1 = fmaf(a, p[lane + 32], acc1);
    }
    size_t o0 = (size_t)b * (Cch * Np) + (size_t)lane * Np + (size_t)n;
    size_t o1 = o0 + (size_t)32 * Np;
    out[o0] = x[o0] + acc0;
    out[o1] = x[o1] + acc1;
}

// ---------------- launch ----------------------------------------------------
extern "C" void kernel_launch(void* const* d_in, const int* in_sizes, int n_in,
                              void* d_out, int out_size) {
    const float* xloc = (const float*)d_in[0];
    const float* x    = (const float*)d_in[1];
    const float* W1   = (const float*)d_in[2];
    const float* g1   = (const float*)d_in[3];
    const float* b1   = (const float*)d_in[4];
    const float* W2   = (const float*)d_in[5];
    const float* g2   = (const float*)d_in[6];
    const float* b2   = (const float*)d_in[7];
    const float* W3   = (const float*)d_in[8];
    const float* g3   = (const float*)d_in[9];
    const float* b3   = (const float*)d_in[10];
    float* out = (float*)d_out;

    size_t knnSmem = sizeof(float4) * Np + sizeof(WarpSel) * KNN_WARPS;
    cudaFuncSetAttribute(k_knn, cudaFuncAttributeMaxDynamicSharedMemorySize, (int)knnSmem);

    k_init<<<128, 256>>>(xloc);
    k_xt<<<dim3(Np / 32, Bz), 256>>>(x);
    k_knn<<<dim3(37, Bz), 256, knnSmem>>>();
    k_feat<<<Bz * Np / 8, 256>>>(W1);
    k_l2<<<Mtot / 256, 256>>>(g1, b1, W2);
    k_l3<<<Mtot / 256, 256>>>(g2, b2, W3);
    k_out<<<Bz * Np / 8, 256>>>(x, g3, b3, out);
}

// round 3
// speedup vs baseline: 1.9631x; 1.3562x over previous
#include <cuda_runtime.h>
#include <cstdint>
#include <math.h>

#define FULLMASK 0xFFFFFFFFu

constexpr int Bz = 8, Np = 4096, Cch = 64, Kn = 30;
constexpr int Mtot = Bz * Np * Kn;           // 983040
constexpr float EPS_BN = 1e-5f;
constexpr float TINYc = 1e-20f;

constexpr int CAND_MAX = 256;

// ---------------- scratch ---------------------------------------------------
__device__ float4 g_pts4[Bz * Np];
__device__ float  g_xT[Bz * Np * Cch];
__device__ int    g_idx[Mtot];
__device__ float  g_h1[6 * Mtot];
__device__ float  g_h2[3 * Mtot];
__device__ float  g_h3[Mtot];
__device__ double g_stats[24];

// ---------------- K0: zero stats, build pts4 -------------------------------
__global__ void __launch_bounds__(256) k_init(const float* __restrict__ xloc) {
    int t = blockIdx.x * blockDim.x + threadIdx.x;
    int stride = gridDim.x * blockDim.x;
    if (t < 24) g_stats[t] = 0.0;
    for (int i = t; i < Bz * Np; i += stride) {
        int b = i >> 12, n = i & 4095;
        const float* p = xloc + b * 3 * Np;
        float px = p[n], py = p[Np + n], pz = p[2 * Np + n];
        float xx = fmaf(pz, pz, fmaf(py, py, px * px));
        g_pts4[i] = make_float4(px, py, pz, xx);
    }
}

// ---------------- K0b: tiled transpose x -> xT [B,N,C] ---------------------
__global__ void __launch_bounds__(256) k_xt(const float* __restrict__ x) {
    __shared__ float s[64][33];
    int b = blockIdx.y;
    int n0 = blockIdx.x * 32;
    int lane = threadIdx.x & 31, w = threadIdx.x >> 5;
    #pragma unroll
    for (int i = 0; i < 8; i++) {
        int c = w * 8 + i;
        s[c][lane] = x[(((b << 6) + c) << 12) + n0 + lane];
    }
    __syncthreads();
    #pragma unroll
    for (int i = 0; i < 8; i++) {
        int e = i * 256 + threadIdx.x;
        int nl = e >> 6, c = e & 63;
        g_xT[(size_t)(((b << 12) + n0 + nl) << 6) + c] = s[c][nl];
    }
}

// ---------------- K1: KNN, 2 queries/warp, sample-threshold + rank select --
struct WarpSel {
    unsigned long long cand[2][CAND_MAX];
};

__device__ __forceinline__ float pdF(float4 q, float4 p) {
    float dot = fmaf(q.z, p.z, fmaf(q.y, p.y, q.x * p.x));
    return fmaf(2.0f, dot, -q.w) - p.w;
}
__device__ __forceinline__ unsigned fkeyU(float f) {
    unsigned b = __float_as_uint(f);
    return b ^ ((unsigned)((int)b >> 31) | 0x80000000u);
}
__device__ __forceinline__ unsigned long long packC(float pd, int j) {
    return ((unsigned long long)fkeyU(pd) << 16) | (unsigned)j;
}

// write top-Kn of cand[0..C) to g_idx[base..base+Kn) by rank
__device__ __forceinline__ void rankWrite(const unsigned long long* cand, int C,
                                          int base, int lane) {
    if (C < Kn) {                            // astronomically rare fallback
        if (lane < Kn) g_idx[base + lane] = (int)(cand[0] & 0xFFFFULL);
        if (lane < C)  g_idx[base + lane] = (int)(cand[lane] & 0xFFFFULL);
        return;
    }
    for (int tb = 0; tb < C; tb += 128) {
        int t0 = tb + lane;
        unsigned long long v0 = (t0 < C)      ? cand[t0]      : 0ULL;
        unsigned long long v1 = (t0 + 32 < C) ? cand[t0 + 32] : 0ULL;
        unsigned long long v2 = (t0 + 64 < C) ? cand[t0 + 64] : 0ULL;
        unsigned long long v3 = (t0 + 96 < C) ? cand[t0 + 96] : 0ULL;
        int r0 = 0, r1 = 0, r2 = 0, r3 = 0;
        #pragma unroll 4
        for (int s = 0; s < C; s++) {
            unsigned long long w2 = cand[s];
            r0 += (w2 > v0); r1 += (w2 > v1);
            r2 += (w2 > v2); r3 += (w2 > v3);
        }
        if (t0 < C      && r0 < Kn) g_idx[base + r0] = (int)(v0 & 0xFFFFULL);
        if (t0 + 32 < C && r1 < Kn) g_idx[base + r1] = (int)(v1 & 0xFFFFULL);
        if (t0 + 64 < C && r2 < Kn) g_idx[base + r2] = (int)(v2 & 0xFFFFULL);
        if (t0 + 96 < C && r3 < Kn) g_idx[base + r3] = (int)(v3 & 0xFFFFULL);
    }
}

__global__ void __launch_bounds__(256, 2) k_knn() {
    extern __shared__ unsigned char smemRaw[];
    float4* sPts = reinterpret_cast<float4*>(smemRaw);
    WarpSel* selA = reinterpret_cast<WarpSel*>(smemRaw + sizeof(float4) * Np);

    int b = blockIdx.y;
    const float4* gp = g_pts4 + b * Np;
    for (int i = threadIdx.x; i < Np; i += 256) sPts[i] = gp[i];
    __syncthreads();

    int wid = threadIdx.x >> 5, lane = threadIdx.x & 31;
    WarpSel& W = selA[wid];
    unsigned laneLT = (lane == 31) ? 0x7FFFFFFFu : ((1u << lane) - 1u);

    for (int m = blockIdx.x * 8 + wid; m < Np / 2; m += gridDim.x * 8) {
        int n0 = m, n1 = m + Np / 2;
        float4 q0 = sPts[n0], q1 = sPts[n1];

        // --- sample pass: contiguous 512-pt window (conflict-free) ---
        int sb = (m & 7) << 9;
        float a1 = -3.4e38f, a2 = -3.4e38f, b1 = -3.4e38f, b2 = -3.4e38f;
        #pragma unroll 4
        for (int t = 0; t < 16; t++) {
            float4 p = sPts[sb + t * 32 + lane];
            float pa = pdF(q0, p), pb = pdF(q1, p);
            if (pa > a2) { if (pa > a1) { a2 = a1; a1 = pa; } else a2 = pa; }
            if (pb > b2) { if (pb > b1) { b2 = b1; b1 = pb; } else b2 = pb; }
        }
        // --- extract 10th & 16th largest (of 64 lane-top2) per query ---
        float Ta10 = 0.f, Ta16 = 0.f, Tb10 = 0.f, Tb16 = 0.f;
        for (int r = 0; r < 16; r++) {
            float va = a1, vb = b1;
            #pragma unroll
            for (int o = 16; o; o >>= 1) {
                va = fmaxf(va, __shfl_xor_sync(FULLMASK, va, o));
                vb = fmaxf(vb, __shfl_xor_sync(FULLMASK, vb, o));
            }
            if (r == 9)  { Ta10 = va; Tb10 = vb; }
            if (r == 15) { Ta16 = va; Tb16 = vb; }
            unsigned wa = __ballot_sync(FULLMASK, a1 == va);
            unsigned wb = __ballot_sync(FULLMASK, b1 == vb);
            if (lane == __ffs(wa) - 1) { a1 = a2; a2 = -3.4e38f; }
            if (lane == __ffs(wb) - 1) { b1 = b2; b2 = -3.4e38f; }
        }

        // --- count+collect scan, 4-way unrolled, both queries per load ---
        float Ta = Ta10, Tb = Tb10;
        unsigned ca, cb;
        for (int att = 0; ; att++) {
            ca = 0; cb = 0;
            for (int j0 = 0; j0 < Np; j0 += 128) {
                float4 p0 = sPts[j0 + lane];
                float4 p1 = sPts[j0 + 32 + lane];
                float4 p2 = sPts[j0 + 64 + lane];
                float4 p3 = sPts[j0 + 96 + lane];
                float pa0 = pdF(q0, p0), pa1 = pdF(q0, p1);
                float pa2 = pdF(q0, p2), pa3 = pdF(q0, p3);
                float pb0 = pdF(q1, p0), pb1 = pdF(q1, p1);
                float pb2 = pdF(q1, p2), pb3 = pdF(q1, p3);
                unsigned ma0 = __ballot_sync(FULLMASK, pa0 > Ta);
                unsigned ma1 = __ballot_sync(FULLMASK, pa1 > Ta);
                unsigned ma2 = __ballot_sync(FULLMASK, pa2 > Ta);
                unsigned ma3 = __ballot_sync(FULLMASK, pa3 > Ta);
                unsigned mb0 = __ballot_sync(FULLMASK, pb0 > Tb);
                unsigned mb1 = __ballot_sync(FULLMASK, pb1 > Tb);
                unsigned mb2 = __ballot_sync(FULLMASK, pb2 > Tb);
                unsigned mb3 = __ballot_sync(FULLMASK, pb3 > Tb);
                unsigned p;
                if (pa0 > Ta) { p = ca + __popc(ma0 & laneLT); if (p < CAND_MAX) W.cand[0][p] = packC(pa0, j0 + lane); }
                ca += __popc(ma0);
                if (pa1 > Ta) { p = ca + __popc(ma1 & laneLT); if (p < CAND_MAX) W.cand[0][p] = packC(pa1, j0 + 32 + lane); }
                ca += __popc(ma1);
                if (pa2 > Ta) { p = ca + __popc(ma2 & laneLT); if (p < CAND_MAX) W.cand[0][p] = packC(pa2, j0 + 64 + lane); }
                ca += __popc(ma2);
                if (pa3 > Ta) { p = ca + __popc(ma3 & laneLT); if (p < CAND_MAX) W.cand[0][p] = packC(pa3, j0 + 96 + lane); }
                ca += __popc(ma3);
                if (pb0 > Tb) { p = cb + __popc(mb0 & laneLT); if (p < CAND_MAX) W.cand[1][p] = packC(pb0, j0 + lane); }
                cb += __popc(mb0);
                if (pb1 > Tb) { p = cb + __popc(mb1 & laneLT); if (p < CAND_MAX) W.cand[1][p] = packC(pb1, j0 + 32 + lane); }
                cb += __popc(mb1);
                if (pb2 > Tb) { p = cb + __popc(mb2 & laneLT); if (p < CAND_MAX) W.cand[1][p] = packC(pb2, j0 + 64 + lane); }
                cb += __popc(mb2);
                if (pb3 > Tb) { p = cb + __popc(mb3 & laneLT); if (p < CAND_MAX) W.cand[1][p] = packC(pb3, j0 + 96 + lane); }
                cb += __popc(mb3);
            }
            if ((ca >= Kn && cb >= Kn) || att == 1) break;
            if (ca < Kn) Ta = Ta16;
            if (cb < Kn) Tb = Tb16;
        }
        __syncwarp();

        rankWrite(W.cand[0], min((int)ca, CAND_MAX), (b * Np + n0) * Kn, lane);
        rankWrite(W.cand[1], min((int)cb, CAND_MAX), (b * Np + n1) * Kn, lane);
        __syncwarp();
    }
}

// ---------------- block-level stat accumulation ----------------------------
template <int NV>
__device__ __forceinline__ void accumStats(const float* vals, float* sAcc, int statBase) {
    #pragma unroll
    for (int v = 0; v < NV; v++) {
        float x = vals[v];
        #pragma unroll
        for (int off = 16; off; off >>= 1) x += __shfl_down_sync(FULLMASK, x, off);
        if ((threadIdx.x & 31) == 0) atomicAdd(&sAcc[v], x);
    }
    __syncthreads();
    if (threadIdx.x < NV) atomicAdd(&g_stats[statBase + threadIdx.x], (double)sAcc[threadIdx.x]);
}

// ---------------- K2: spherical features + layer1 + stats ------------------
__global__ void __launch_bounds__(256) k_feat(const float* __restrict__ W1) {
    __shared__ float sW[36];
    __shared__ float sAcc[12];
    int tid = threadIdx.x;
    if (tid < 36) sW[tid] = W1[tid];
    if (tid < 12) sAcc[tid] = 0.f;
    __syncthreads();
    int wid = tid >> 5, lane = tid & 31;
    int r = blockIdx.x * 8 + wid;
    int b = r >> 12;
    float vals[12];
    #pragma unroll
    for (int v = 0; v < 12; v++) vals[v] = 0.f;
    if (lane < Kn) {
        int e = r * Kn + lane;
        int j = g_idx[e];
        float4 pn = g_pts4[r];
        float4 pj = g_pts4[(b << 12) + j];
        float xr = pj.x - pn.x, yr = pj.y - pn.y, zr = pj.z - pn.z;
        float sxy2 = fmaf(yr, yr, xr * xr);
        float r2 = fmaf(zr, zr, sxy2);
        float rho = sqrtf(fmaxf(r2, TINYc));
        float sxy = sqrtf(fmaxf(sxy2, TINYc));
        float theta = (r2 < TINYc) ? 0.f : atan2f(zr, sxy);
        float phi = (sxy2 < TINYc) ? 0.f : atan2f(yr, xr);
        float mn = (rho + theta + phi) * (1.f / 3.f);
        float f[6] = {rho, theta, phi, rho - mn, theta - mn, phi - mn};
        #pragma unroll
        for (int o = 0; o < 6; o++) {
            float h = 0.f;
            #pragma unroll
            for (int i2 = 0; i2 < 6; i2++) h = fmaf(sW[o * 6 + i2], f[i2], h);
            g_h1[o * Mtot + e] = h;
            vals[o] = h; vals[6 + o] = h * h;
        }
    }
    accumStats<12>(vals, sAcc, 0);
}

__device__ __forceinline__ float lrelu02(float t) { return t > 0.f ? t : 0.2f * t; }

// ---------------- K3: BN1 + lrelu + layer2 + stats (float4) ----------------
__global__ void __launch_bounds__(256) k_l2(const float* __restrict__ gma,
                                            const float* __restrict__ bta,
                                            const float* __restrict__ W2) {
    __shared__ float sMu[6], sIs[6], sG[6], sB[6], sW[18], sAcc[6];
    int tid = threadIdx.x;
    if (tid < 6) {
        double s = g_stats[tid], sq = g_stats[6 + tid];
        double mu = s / (double)Mtot;
        double var = sq / (double)Mtot - mu * mu;
        sMu[tid] = (float)mu;
        sIs[tid] = (float)(1.0 / sqrt(var + (double)EPS_BN));
        sG[tid] = gma[tid]; sB[tid] = bta[tid];
        sAcc[tid] = 0.f;
    }
    if (tid < 18) sW[tid] = W2[tid];
    __syncthreads();
    int e4 = (blockIdx.x * 256 + tid) * 4;
    float4 a[6];
    #pragma unroll
    for (int i = 0; i < 6; i++) {
        float4 h = *reinterpret_cast<const float4*>(&g_h1[i * Mtot + e4]);
        float sc = sIs[i] * sG[i], mu = sMu[i], bb = sB[i];
        a[i].x = lrelu02(fmaf((h.x - mu), sc, bb));
        a[i].y = lrelu02(fmaf((h.y - mu), sc, bb));
        a[i].z = lrelu02(fmaf((h.z - mu), sc, bb));
        a[i].w = lrelu02(fmaf((h.w - mu), sc, bb));
    }
    float vals[6];
    #pragma unroll
    for (int o = 0; o < 3; o++) {
        float4 h = make_float4(0.f, 0.f, 0.f, 0.f);
        #pragma unroll
        for (int i = 0; i < 6; i++) {
            float w = sW[o * 6 + i];
            h.x = fmaf(w, a[i].x, h.x); h.y = fmaf(w, a[i].y, h.y);
            h.z = fmaf(w, a[i].z, h.z); h.w = fmaf(w, a[i].w, h.w);
        }
        *reinterpret_cast<float4*>(&g_h2[o * Mtot + e4]) = h;
        vals[o] = (h.x + h.y) + (h.z + h.w);
        vals[3 + o] = fmaf(h.x, h.x, h.y * h.y) + fmaf(h.z, h.z, h.w * h.w);
    }
    accumStats<6>(vals, sAcc, 12);
}

// ---------------- K4: BN2 + lrelu + layer3 + stats (float4) ----------------
__global__ void __launch_bounds__(256) k_l3(const float* __restrict__ gma,
                                            const float* __restrict__ bta,
                                            const float* __restrict__ W3) {
    __shared__ float sMu[3], sIs[3], sG[3], sB[3], sW[3], sAcc[2];
    int tid = threadIdx.x;
    if (tid < 3) {
        double s = g_stats[12 + tid], sq = g_stats[15 + tid];
        double mu = s / (double)Mtot;
        double var = sq / (double)Mtot - mu * mu;
        sMu[tid] = (float)mu;
        sIs[tid] = (float)(1.0 / sqrt(var + (double)EPS_BN));
        sG[tid] = gma[tid]; sB[tid] = bta[tid];
        sW[tid] = W3[tid];
    }
    if (tid < 2) sAcc[tid] = 0.f;
    __syncthreads();
    int e4 = (blockIdx.x * 256 + tid) * 4;
    float4 h = make_float4(0.f, 0.f, 0.f, 0.f);
    #pragma unroll
    for (int i = 0; i < 3; i++) {
        float4 hv = *reinterpret_cast<const float4*>(&g_h2[i * Mtot + e4]);
        float sc = sIs[i] * sG[i], mu = sMu[i], bb = sB[i], w = sW[i];
        h.x = fmaf(w, lrelu02(fmaf((hv.x - mu), sc, bb)), h.x);
        h.y = fmaf(w, lrelu02(fmaf((hv.y - mu), sc, bb)), h.y);
        h.z = fmaf(w, lrelu02(fmaf((hv.z - mu), sc, bb)), h.z);
        h.w = fmaf(w, lrelu02(fmaf((hv.w - mu), sc, bb)), h.w);
    }
    *reinterpret_cast<float4*>(&g_h3[e4]) = h;
    float vals[2];
    vals[0] = (h.x + h.y) + (h.z + h.w);
    vals[1] = fmaf(h.x, h.x, h.y * h.y) + fmaf(h.z, h.z, h.w * h.w);
    accumStats<2>(vals, sAcc, 18);
}

// ---------------- K5: BN3 + lrelu + softmax + aggregate --------------------
__global__ void __launch_bounds__(256) k_out(const float* __restrict__ x,
                                             const float* __restrict__ g3,
                                             const float* __restrict__ b3,
                                             float* __restrict__ out) {
    __shared__ float sAtt[8][Kn];
    __shared__ int sJ[8][Kn];
    __shared__ float sMu, sIs;
    int tid = threadIdx.x, wid = tid >> 5, lane = tid & 31;
    if (tid == 0) {
        double s = g_stats[18], sq = g_stats[19];
        double mu = s / (double)Mtot;
        double var = sq / (double)Mtot - mu * mu;
        sMu = (float)mu;
        sIs = (float)(1.0 / sqrt(var + (double)EPS_BN));
    }
    __syncthreads();
    int r = blockIdx.x * 8 + wid;
    int b = r >> 12, n = r & 4095;
    float gv = g3[0], bv = b3[0];
    float logit = -INFINITY;
    if (lane < Kn) {
        float h = g_h3[r * Kn + lane];
        float t = fmaf((h - sMu) * sIs, gv, bv);
        logit = t > 0.f ? t : 0.2f * t;
    }
    float mx = logit;
    #pragma unroll
    for (int off = 16; off; off >>= 1) mx = fmaxf(mx, __shfl_xor_sync(FULLMASK, mx, off));
    float ex = (lane < Kn) ? expf(logit - mx) : 0.f;
    float sm = ex;
    #pragma unroll
    for (int off = 16; off; off >>= 1) sm += __shfl_xor_sync(FULLMASK, sm, off);
    float att = ex / sm;
    if (lane < Kn) {
        sAtt[wid][lane] = att;
        sJ[wid][lane] = g_idx[r * Kn + lane];
    }
    __syncwarp();
    float acc0 = 0.f, acc1 = 0.f;
    const float* xb = g_xT + (size_t)(b << 12) * Cch;
    #pragma unroll 5
    for (int kk = 0; kk < Kn; kk++) {
        const float* p = xb + sJ[wid][kk] * Cch;
        float a = sAtt[wid][kk];
        acc0 = fmaf(a, p[lane], acc0);
        acc1 = fmaf(a, p[lane + 32], acc1);
    }
    size_t o0 = (size_t)b * (Cch * Np) + (size_t)lane * Np + (size_t)n;
    size_t o1 = o0 + (size_t)32 * Np;
    out[o0] = x[o0] + acc0;
    out[o1] = x[o1] + acc1;
}

// ---------------- launch ----------------------------------------------------
extern "C" void kernel_launch(void* const* d_in, const int* in_sizes, int n_in,
                              void* d_out, int out_size) {
    const float* xloc = (const float*)d_in[0];
    const float* x    = (const float*)d_in[1];
    const float* W1   = (const float*)d_in[2];
    const float* g1   = (const float*)d_in[3];
    const float* b1   = (const float*)d_in[4];
    const float* W2   = (const float*)d_in[5];
    const float* g2   = (const float*)d_in[6];
    const float* b2   = (const float*)d_in[7];
    const float* W3   = (const float*)d_in[8];
    const float* g3   = (const float*)d_in[9];
    const float* b3   = (const float*)d_in[10];
    float* out = (float*)d_out;

    size_t knnSmem = sizeof(float4) * Np + sizeof(WarpSel) * 8;
    cudaFuncSetAttribute(k_knn, cudaFuncAttributeMaxDynamicSharedMemorySize, (int)knnSmem);

    k_init<<<128, 256>>>(xloc);
    k_xt<<<dim3(Np / 32, Bz), 256>>>(x);
    k_knn<<<dim3(32, Bz), 256, knnSmem>>>();
    k_feat<<<Bz * Np / 8, 256>>>(W1);
    k_l2<<<Mtot / 1024, 256>>>(g1, b1, W2);
    k_l3<<<Mtot / 1024, 256>>>(g2, b2, W3);
    k_out<<<Bz * Np / 8, 256>>>(x, g3, b3, out);
}

// round 4
// speedup vs baseline: 2.2565x; 1.1495x over previous
#include <cuda_runtime.h>
#include <cstdint>
#include <math.h>

#define FULLMASK 0xFFFFFFFFu

constexpr int Bz = 8, Np = 4096, Cch = 64, Kn = 30;
constexpr int Mtot = Bz * Np * Kn;           // 983040
constexpr float EPS_BN = 1e-5f;
constexpr float TINYc = 1e-20f;

constexpr int CAND_MAX = 192;
constexpr int KNN_TPB = 512;                 // 16 warps
constexpr int KNN_WPB = KNN_TPB / 32;

// ---------------- scratch ---------------------------------------------------
__device__ float4 g_pts4[Bz * Np];
__device__ float  g_xT[Bz * Np * Cch];
__device__ int    g_idx[Mtot];
__device__ float  g_h1[6 * Mtot];
__device__ float  g_h2[3 * Mtot];
__device__ float  g_h3[Mtot];
__device__ double g_stats[24];

// ---------------- K0: zero stats, build pts4 -------------------------------
__global__ void __launch_bounds__(256) k_init(const float* __restrict__ xloc) {
    int t = blockIdx.x * blockDim.x + threadIdx.x;
    int stride = gridDim.x * blockDim.x;
    if (t < 24) g_stats[t] = 0.0;
    for (int i = t; i < Bz * Np; i += stride) {
        int b = i >> 12, n = i & 4095;
        const float* p = xloc + b * 3 * Np;
        float px = p[n], py = p[Np + n], pz = p[2 * Np + n];
        float xx = fmaf(pz, pz, fmaf(py, py, px * px));
        g_pts4[i] = make_float4(px, py, pz, xx);
    }
}

// ---------------- K0b: tiled transpose x -> xT [B,N,C] ---------------------
__global__ void __launch_bounds__(256) k_xt(const float* __restrict__ x) {
    __shared__ float s[64][33];
    int b = blockIdx.y;
    int n0 = blockIdx.x * 32;
    int lane = threadIdx.x & 31, w = threadIdx.x >> 5;
    #pragma unroll
    for (int i = 0; i < 8; i++) {
        int c = w * 8 + i;
        s[c][lane] = x[(((b << 6) + c) << 12) + n0 + lane];
    }
    __syncthreads();
    #pragma unroll
    for (int i = 0; i < 8; i++) {
        int e = i * 256 + threadIdx.x;
        int nl = e >> 6, c = e & 63;
        g_xT[(size_t)(((b << 12) + n0 + nl) << 6) + c] = s[c][nl];
    }
}

// ---------------- K1: KNN, 2 queries/warp, sample-threshold + rank select --
struct WarpSel {
    unsigned long long cand[2][CAND_MAX];
};

__device__ __forceinline__ float pdF(float4 q, float4 p) {
    float dot = fmaf(q.z, p.z, fmaf(q.y, p.y, q.x * p.x));
    return fmaf(2.0f, dot, -q.w) - p.w;
}
__device__ __forceinline__ unsigned fkeyU(float f) {
    unsigned b = __float_as_uint(f);
    return b ^ ((unsigned)((int)b >> 31) | 0x80000000u);
}
__device__ __forceinline__ unsigned long long packC(float pd, int j) {
    return ((unsigned long long)fkeyU(pd) << 16) | (unsigned)j;
}

__device__ __forceinline__ void rankWrite(const unsigned long long* cand, int C,
                                          int base, int lane) {
    if (C < Kn) {                            // astronomically rare fallback
        if (lane < Kn) g_idx[base + lane] = (int)(cand[0] & 0xFFFFULL);
        if (lane < C)  g_idx[base + lane] = (int)(cand[lane] & 0xFFFFULL);
        return;
    }
    for (int tb = 0; tb < C; tb += 128) {
        int t0 = tb + lane;
        unsigned long long v0 = (t0 < C)      ? cand[t0]      : 0ULL;
        unsigned long long v1 = (t0 + 32 < C) ? cand[t0 + 32] : 0ULL;
        unsigned long long v2 = (t0 + 64 < C) ? cand[t0 + 64] : 0ULL;
        unsigned long long v3 = (t0 + 96 < C) ? cand[t0 + 96] : 0ULL;
        int r0 = 0, r1 = 0, r2 = 0, r3 = 0;
        #pragma unroll 4
        for (int s = 0; s < C; s++) {
            unsigned long long w2 = cand[s];
            r0 += (w2 > v0); r1 += (w2 > v1);
            r2 += (w2 > v2); r3 += (w2 > v3);
        }
        if (t0 < C      && r0 < Kn) g_idx[base + r0] = (int)(v0 & 0xFFFFULL);
        if (t0 + 32 < C && r1 < Kn) g_idx[base + r1] = (int)(v1 & 0xFFFFULL);
        if (t0 + 64 < C && r2 < Kn) g_idx[base + r2] = (int)(v2 & 0xFFFFULL);
        if (t0 + 96 < C && r3 < Kn) g_idx[base + r3] = (int)(v3 & 0xFFFFULL);
    }
}

__global__ void __launch_bounds__(KNN_TPB, 2) k_knn() {
    extern __shared__ unsigned char smemRaw[];
    float4* sPts = reinterpret_cast<float4*>(smemRaw);
    WarpSel* selA = reinterpret_cast<WarpSel*>(smemRaw + sizeof(float4) * Np);

    int b = blockIdx.y;
    const float4* gp = g_pts4 + b * Np;
    for (int i = threadIdx.x; i < Np; i += KNN_TPB) sPts[i] = gp[i];
    __syncthreads();

    int wid = threadIdx.x >> 5, lane = threadIdx.x & 31;
    WarpSel& W = selA[wid];
    unsigned laneLT = (lane == 31) ? 0x7FFFFFFFu : ((1u << lane) - 1u);

    for (int m = blockIdx.x * KNN_WPB + wid; m < Np / 2; m += gridDim.x * KNN_WPB) {
        int n0 = m, n1 = m + Np / 2;
        float4 q0 = sPts[n0], q1 = sPts[n1];

        // --- sample pass: contiguous 512-pt window (conflict-free) ---
        int sb = (m & 7) << 9;
        float a1 = -3.4e38f, a2 = -3.4e38f, b1 = -3.4e38f, b2 = -3.4e38f;
        #pragma unroll 4
        for (int t = 0; t < 16; t++) {
            float4 p = sPts[sb + t * 32 + lane];
            float pa = pdF(q0, p), pb = pdF(q1, p);
            if (pa > a2) { if (pa > a1) { a2 = a1; a1 = pa; } else a2 = pa; }
            if (pb > b2) { if (pb > b1) { b2 = b1; b1 = pb; } else b2 = pb; }
        }
        // --- extract 8th & 16th largest (of 64 lane-top2) per query ---
        float Ta8 = 0.f, Ta16 = 0.f, Tb8 = 0.f, Tb16 = 0.f;
        for (int r = 0; r < 16; r++) {
            float va = a1, vb = b1;
            #pragma unroll
            for (int o = 16; o; o >>= 1) {
                va = fmaxf(va, __shfl_xor_sync(FULLMASK, va, o));
                vb = fmaxf(vb, __shfl_xor_sync(FULLMASK, vb, o));
            }
            if (r == 7)  { Ta8 = va; Tb8 = vb; }
            if (r == 15) { Ta16 = va; Tb16 = vb; }
            unsigned wa = __ballot_sync(FULLMASK, a1 == va);
            unsigned wb = __ballot_sync(FULLMASK, b1 == vb);
            if (lane == __ffs(wa) - 1) { a1 = a2; a2 = -3.4e38f; }
            if (lane == __ffs(wb) - 1) { b1 = b2; b2 = -3.4e38f; }
        }

        // --- count+collect scan, 4-way unrolled, both queries per load ---
        float Ta = Ta8, Tb = Tb8;
        unsigned ca, cb;
        for (int att = 0; ; att++) {
            ca = 0; cb = 0;
            for (int j0 = 0; j0 < Np; j0 += 128) {
                float4 p0 = sPts[j0 + lane];
                float4 p1 = sPts[j0 + 32 + lane];
                float4 p2 = sPts[j0 + 64 + lane];
                float4 p3 = sPts[j0 + 96 + lane];
                float pa0 = pdF(q0, p0), pa1 = pdF(q0, p1);
                float pa2 = pdF(q0, p2), pa3 = pdF(q0, p3);
                float pb0 = pdF(q1, p0), pb1 = pdF(q1, p1);
                float pb2 = pdF(q1, p2), pb3 = pdF(q1, p3);
                unsigned ma0 = __ballot_sync(FULLMASK, pa0 > Ta);
                unsigned ma1 = __ballot_sync(FULLMASK, pa1 > Ta);
                unsigned ma2 = __ballot_sync(FULLMASK, pa2 > Ta);
                unsigned ma3 = __ballot_sync(FULLMASK, pa3 > Ta);
                unsigned mb0 = __ballot_sync(FULLMASK, pb0 > Tb);
                unsigned mb1 = __ballot_sync(FULLMASK, pb1 > Tb);
                unsigned mb2 = __ballot_sync(FULLMASK, pb2 > Tb);
                unsigned mb3 = __ballot_sync(FULLMASK, pb3 > Tb);
                unsigned p;
                if (pa0 > Ta) { p = ca + __popc(ma0 & laneLT); if (p < CAND_MAX) W.cand[0][p] = packC(pa0, j0 + lane); }
                ca += __popc(ma0);
                if (pa1 > Ta) { p = ca + __popc(ma1 & laneLT); if (p < CAND_MAX) W.cand[0][p] = packC(pa1, j0 + 32 + lane); }
                ca += __popc(ma1);
                if (pa2 > Ta) { p = ca + __popc(ma2 & laneLT); if (p < CAND_MAX) W.cand[0][p] = packC(pa2, j0 + 64 + lane); }
                ca += __popc(ma2);
                if (pa3 > Ta) { p = ca + __popc(ma3 & laneLT); if (p < CAND_MAX) W.cand[0][p] = packC(pa3, j0 + 96 + lane); }
                ca += __popc(ma3);
                if (pb0 > Tb) { p = cb + __popc(mb0 & laneLT); if (p < CAND_MAX) W.cand[1][p] = packC(pb0, j0 + lane); }
                cb += __popc(mb0);
                if (pb1 > Tb) { p = cb + __popc(mb1 & laneLT); if (p < CAND_MAX) W.cand[1][p] = packC(pb1, j0 + 32 + lane); }
                cb += __popc(mb1);
                if (pb2 > Tb) { p = cb + __popc(mb2 & laneLT); if (p < CAND_MAX) W.cand[1][p] = packC(pb2, j0 + 64 + lane); }
                cb += __popc(mb2);
                if (pb3 > Tb) { p = cb + __popc(mb3 & laneLT); if (p < CAND_MAX) W.cand[1][p] = packC(pb3, j0 + 96 + lane); }
                cb += __popc(mb3);
            }
            if ((ca >= Kn && cb >= Kn) || att == 1) break;
            if (ca < Kn) Ta = Ta16;
            if (cb < Kn) Tb = Tb16;
        }
        __syncwarp();

        rankWrite(W.cand[0], min((int)ca, CAND_MAX), (b * Np + n0) * Kn, lane);
        rankWrite(W.cand[1], min((int)cb, CAND_MAX), (b * Np + n1) * Kn, lane);
        __syncwarp();
    }
}

// ---------------- block-level stat accumulation ----------------------------
template <int NV>
__device__ __forceinline__ void accumStats(const float* vals, float* sAcc, int statBase) {
    #pragma unroll
    for (int v = 0; v < NV; v++) {
        float x = vals[v];
        #pragma unroll
        for (int off = 16; off; off >>= 1) x += __shfl_down_sync(FULLMASK, x, off);
        if ((threadIdx.x & 31) == 0) atomicAdd(&sAcc[v], x);
    }
    __syncthreads();
    if (threadIdx.x < NV) atomicAdd(&g_stats[statBase + threadIdx.x], (double)sAcc[threadIdx.x]);
}

// ---------------- K2: spherical features + layer1 + stats ------------------
// grid 512; each warp processes 8 rows; stats accumulated in registers.
__global__ void __launch_bounds__(256) k_feat(const float* __restrict__ W1) {
    __shared__ float sW[36];
    __shared__ float sAcc[12];
    int tid = threadIdx.x;
    if (tid < 36) sW[tid] = W1[tid];
    if (tid < 12) sAcc[tid] = 0.f;
    __syncthreads();
    int wid = tid >> 5, lane = tid & 31;
    float acc[12];
    #pragma unroll
    for (int v = 0; v < 12; v++) acc[v] = 0.f;

    #pragma unroll 2
    for (int i = 0; i < 8; i++) {
        int r = blockIdx.x * 64 + i * 8 + wid;
        int b = r >> 12;
        if (lane < Kn) {
            int e = r * Kn + lane;
            int j = g_idx[e];
            float4 pn = g_pts4[r];
            float4 pj = g_pts4[(b << 12) + j];
            float xr = pj.x - pn.x, yr = pj.y - pn.y, zr = pj.z - pn.z;
            float sxy2 = fmaf(yr, yr, xr * xr);
            float r2 = fmaf(zr, zr, sxy2);
            float rho = sqrtf(fmaxf(r2, TINYc));
            float sxy = sqrtf(fmaxf(sxy2, TINYc));
            float theta = (r2 < TINYc) ? 0.f : atan2f(zr, sxy);
            float phi = (sxy2 < TINYc) ? 0.f : atan2f(yr, xr);
            float mn = (rho + theta + phi) * (1.f / 3.f);
            float f[6] = {rho, theta, phi, rho - mn, theta - mn, phi - mn};
            #pragma unroll
            for (int o = 0; o < 6; o++) {
                float h = 0.f;
                #pragma unroll
                for (int i2 = 0; i2 < 6; i2++) h = fmaf(sW[o * 6 + i2], f[i2], h);
                g_h1[o * Mtot + e] = h;
                acc[o] += h; acc[6 + o] = fmaf(h, h, acc[6 + o]);
            }
        }
    }
    accumStats<12>(acc, sAcc, 0);
}

__device__ __forceinline__ float lrelu02(float t) { return t > 0.f ? t : 0.2f * t; }

// ---------------- K3: BN1 + lrelu + layer2 + stats (float4) ----------------
__global__ void __launch_bounds__(256) k_l2(const float* __restrict__ gma,
                                            const float* __restrict__ bta,
                                            const float* __restrict__ W2) {
    __shared__ float sMu[6], sIs[6], sG[6], sB[6], sW[18], sAcc[6];
    int tid = threadIdx.x;
    if (tid < 6) {
        double s = g_stats[tid], sq = g_stats[6 + tid];
        double mu = s / (double)Mtot;
        double var = sq / (double)Mtot - mu * mu;
        sMu[tid] = (float)mu;
        sIs[tid] = (float)(1.0 / sqrt(var + (double)EPS_BN));
        sG[tid] = gma[tid]; sB[tid] = bta[tid];
        sAcc[tid] = 0.f;
    }
    if (tid < 18) sW[tid] = W2[tid];
    __syncthreads();
    int e4 = (blockIdx.x * 256 + tid) * 4;
    float4 a[6];
    #pragma unroll
    for (int i = 0; i < 6; i++) {
        float4 h = *reinterpret_cast<const float4*>(&g_h1[i * Mtot + e4]);
        float sc = sIs[i] * sG[i], mu = sMu[i], bb = sB[i];
        a[i].x = lrelu02(fmaf((h.x - mu), sc, bb));
        a[i].y = lrelu02(fmaf((h.y - mu), sc, bb));
        a[i].z = lrelu02(fmaf((h.z - mu), sc, bb));
        a[i].w = lrelu02(fmaf((h.w - mu), sc, bb));
    }
    float vals[6];
    #pragma unroll
    for (int o = 0; o < 3; o++) {
        float4 h = make_float4(0.f, 0.f, 0.f, 0.f);
        #pragma unroll
        for (int i = 0; i < 6; i++) {
            float w = sW[o * 6 + i];
            h.x = fmaf(w, a[i].x, h.x); h.y = fmaf(w, a[i].y, h.y);
            h.z = fmaf(w, a[i].z, h.z); h.w = fmaf(w, a[i].w, h.w);
        }
        *reinterpret_cast<float4*>(&g_h2[o * Mtot + e4]) = h;
        vals[o] = (h.x + h.y) + (h.z + h.w);
        vals[3 + o] = fmaf(h.x, h.x, h.y * h.y) + fmaf(h.z, h.z, h.w * h.w);
    }
    accumStats<6>(vals, sAcc, 12);
}

// ---------------- K4: BN2 + lrelu + layer3 + stats (float4) ----------------
__global__ void __launch_bounds__(256) k_l3(const float* __restrict__ gma,
                                            const float* __restrict__ bta,
                                            const float* __restrict__ W3) {
    __shared__ float sMu[3], sIs[3], sG[3], sB[3], sW[3], sAcc[2];
    int tid = threadIdx.x;
    if (tid < 3) {
        double s = g_stats[12 + tid], sq = g_stats[15 + tid];
        double mu = s / (double)Mtot;
        double var = sq / (double)Mtot - mu * mu;
        sMu[tid] = (float)mu;
        sIs[tid] = (float)(1.0 / sqrt(var + (double)EPS_BN));
        sG[tid] = gma[tid]; sB[tid] = bta[tid];
        sW[tid] = W3[tid];
    }
    if (tid < 2) sAcc[tid] = 0.f;
    __syncthreads();
    int e4 = (blockIdx.x * 256 + tid) * 4;
    float4 h = make_float4(0.f, 0.f, 0.f, 0.f);
    #pragma unroll
    for (int i = 0; i < 3; i++) {
        float4 hv = *reinterpret_cast<const float4*>(&g_h2[i * Mtot + e4]);
        float sc = sIs[i] * sG[i], mu = sMu[i], bb = sB[i], w = sW[i];
        h.x = fmaf(w, lrelu02(fmaf((hv.x - mu), sc, bb)), h.x);
        h.y = fmaf(w, lrelu02(fmaf((hv.y - mu), sc, bb)), h.y);
        h.z = fmaf(w, lrelu02(fmaf((hv.z - mu), sc, bb)), h.z);
        h.w = fmaf(w, lrelu02(fmaf((hv.w - mu), sc, bb)), h.w);
    }
    *reinterpret_cast<float4*>(&g_h3[e4]) = h;
    float vals[2];
    vals[0] = (h.x + h.y) + (h.z + h.w);
    vals[1] = fmaf(h.x, h.x, h.y * h.y) + fmaf(h.z, h.z, h.w * h.w);
    accumStats<2>(vals, sAcc, 18);
}

// ---------------- K5: BN3 + lrelu + softmax + aggregate --------------------
__global__ void __launch_bounds__(256) k_out(const float* __restrict__ x,
                                             const float* __restrict__ g3,
                                             const float* __restrict__ b3,
                                             float* __restrict__ out) {
    __shared__ float sAtt[8][Kn];
    __shared__ int sJ[8][Kn];
    __shared__ float sMu, sIs;
    int tid = threadIdx.x, wid = tid >> 5, lane = tid & 31;
    if (tid == 0) {
        double s = g_stats[18], sq = g_stats[19];
        double mu = s / (double)Mtot;
        double var = sq / (double)Mtot - mu * mu;
        sMu = (float)mu;
        sIs = (float)(1.0 / sqrt(var + (double)EPS_BN));
    }
    __syncthreads();
    int r = blockIdx.x * 8 + wid;
    int b = r >> 12, n = r & 4095;
    float gv = g3[0], bv = b3[0];
    float logit = -INFINITY;
    if (lane < Kn) {
        float h = g_h3[r * Kn + lane];
        float t = fmaf((h - sMu) * sIs, gv, bv);
        logit = t > 0.f ? t : 0.2f * t;
    }
    float mx = logit;
    #pragma unroll
    for (int off = 16; off; off >>= 1) mx = fmaxf(mx, __shfl_xor_sync(FULLMASK, mx, off));
    float ex = (lane < Kn) ? expf(logit - mx) : 0.f;
    float sm = ex;
    #pragma unroll
    for (int off = 16; off; off >>= 1) sm += __shfl_xor_sync(FULLMASK, sm, off);
    float att = ex / sm;
    if (lane < Kn) {
        sAtt[wid][lane] = att;
        sJ[wid][lane] = g_idx[r * Kn + lane];
    }
    __syncwarp();
    float acc0 = 0.f, acc1 = 0.f;
    const float* xb = g_xT + (size_t)(b << 12) * Cch;
    #pragma unroll 5
    for (int kk = 0; kk < Kn; kk++) {
        const float* p = xb + sJ[wid][kk] * Cch;
        float a = sAtt[wid][kk];
        acc0 = fmaf(a, p[lane], acc0);
        acc1 = fmaf(a, p[lane + 32], acc1);
    }
    size_t o0 = (size_t)b * (Cch * Np) + (size_t)lane * Np + (size_t)n;
    size_t o1 = o0 + (size_t)32 * Np;
    out[o0] = x[o0] + acc0;
    out[o1] = x[o1] + acc1;
}

// ---------------- launch ----------------------------------------------------
extern "C" void kernel_launch(void* const* d_in, const int* in_sizes, int n_in,
                              void* d_out, int out_size) {
    const float* xloc = (const float*)d_in[0];
    const float* x    = (const float*)d_in[1];
    const float* W1   = (const float*)d_in[2];
    const float* g1   = (const float*)d_in[3];
    const float* b1   = (const float*)d_in[4];
    const float* W2   = (const float*)d_in[5];
    const float* g2   = (const float*)d_in[6];
    const float* b2   = (const float*)d_in[7];
    const float* W3   = (const float*)d_in[8];
    const float* g3   = (const float*)d_in[9];
    const float* b3   = (const float*)d_in[10];
    float* out = (float*)d_out;

    size_t knnSmem = sizeof(float4) * Np + sizeof(WarpSel) * KNN_WPB;
    cudaFuncSetAttribute(k_knn, cudaFuncAttributeMaxDynamicSharedMemorySize, (int)knnSmem);

    k_init<<<128, 256>>>(xloc);
    k_xt<<<dim3(Np / 32, Bz), 256>>>(x);
    k_knn<<<dim3(37, Bz), KNN_TPB, knnSmem>>>();
    k_feat<<<512, 256>>>(W1);
    k_l2<<<Mtot / 1024, 256>>>(g1, b1, W2);
    k_l3<<<Mtot / 1024, 256>>>(g2, b2, W3);
    k_out<<<Bz * Np / 8, 256>>>(x, g3, b3, out);
}